// round 16
// baseline (speedup 1.0000x reference)
#include <cuda_runtime.h>
#include <cstdint>
#include <math.h>

#define BATCH   2048
#define IN_DIM  512
#define NUM_OUT 256

#define BM 64
#define BN 128
#define BK 16
#define NTHREADS 128
#define KSPLIT 4
#define KCHUNK (IN_DIM / KSPLIT)    // 128
#define NSTEPS (KCHUNK / BK)        // 8

// dynamic smem: ws[128][128] floats (64KB) + xs[3][BK][132]
#define WS_FLOATS (KCHUNK * BN)               // 16384
#define XS_STRIDE (2 * BM + 4)                // 132
#define XS_FLOATS (3 * BK * XS_STRIDE)        // 6336
#define SMEM_BYTES ((WS_FLOATS + XS_FLOATS) * 4)

typedef unsigned long long ull;

// Partial products per K-chunk: 8 MB
__device__ float g_part[KSPLIT][BATCH * NUM_OUT];

__device__ __forceinline__ ull ffma2(ull a, ull b, ull c) {
    ull d;
    asm("fma.rn.f32x2 %0, %1, %2, %3;" : "=l"(d) : "l"(a), "l"(b), "l"(c));
    return d;
}
__device__ __forceinline__ ull fmul2(ull a, ull b) {
    ull d;
    asm("mul.rn.f32x2 %0, %1, %2;" : "=l"(d) : "l"(a), "l"(b));
    return d;
}

// 64(M) x 128(N) tile per CTA over one 128-K chunk. Thread tile 8x8.
// Sigmoid fused: each CTA builds its own -sigmoid(5W) tile in smem once
// (no precompute kernel, no per-step w traffic). ws row layout is
// piece-permuted: 16B piece p -> phys chunk (p even ? p/2 : 16+p/2), so the
// compute's two w LDS.128 per thread hit contiguous 256B halves.
// xs triple-buffered -> one barrier per step.
__global__ void __launch_bounds__(NTHREADS, 2)
logic_kernel(const float* __restrict__ x, const float* __restrict__ Wraw) {
    extern __shared__ __align__(16) float smem[];
    float* ws  = smem;                // [KCHUNK][BN] piece-permuted per row
    float* xsb = smem + WS_FLOATS;    // [3][BK][XS_STRIDE]
#define XS(b, k, i) xsb[((b) * BK + (k)) * XS_STRIDE + (i)]

    const int tid = threadIdx.x;
    const int bm0 = blockIdx.x * BM;
    const int bn  = blockIdx.y;          // 0..1
    const int kz  = blockIdx.z;          // K-chunk
    const int kbase = kz * KCHUNK;

    const int cg = tid & 15;   // col-group: 8 cols each
    const int rg = tid >> 4;   // row-group: 8 rows each

    // x staging: row xm (0..63), k-half xq (8 k's each)
    const int xm = tid & 63;
    const int xq = tid >> 6;   // 0 or 1
    const int kb = xq * 8;

    const ull ONE2 = 0x3F8000003F800000ULL;
    ull acc[8][4];
#pragma unroll
    for (int i = 0; i < 8; ++i)
#pragma unroll
        for (int j = 0; j < 4; ++j) acc[i][j] = ONE2;

    const float* xrow = x + (ull)(bm0 + xm) * IN_DIM + kbase + xq * 8;

#define XDUP(b, slot, val) do {                                            \
    float2 _p; _p.x = 1.0f - (val); _p.y = _p.x;                           \
    *reinterpret_cast<float2*>(&XS(b, kb + (slot), 2 * xm)) = _p;          \
} while (0)

    // ---------------- prologue ----------------
    {
        // w tile: thread handles logical column f = tid of this CTA's 128-o
        // slice; phys column from inverse piece permutation.
        const float* wrow = Wraw + (ull)(bn * BN + tid) * IN_DIM + kbase;
        const int p = tid >> 2, r = tid & 3;
        const int wcol = (((p & 1) ? 16 + (p >> 1) : (p >> 1)) << 2) + r;
#pragma unroll
        for (int c = 0; c < KCHUNK / 4; ++c) {
            float4 v = *reinterpret_cast<const float4*>(wrow + c * 4);
            ws[(c * 4 + 0) * BN + wcol] = -1.0f / (1.0f + __expf(-5.0f * v.x));
            ws[(c * 4 + 1) * BN + wcol] = -1.0f / (1.0f + __expf(-5.0f * v.y));
            ws[(c * 4 + 2) * BN + wcol] = -1.0f / (1.0f + __expf(-5.0f * v.z));
            ws[(c * 4 + 3) * BN + wcol] = -1.0f / (1.0f + __expf(-5.0f * v.w));
        }
        // x buffer 0
        float4 a = *reinterpret_cast<const float4*>(xrow + 0);
        float4 b = *reinterpret_cast<const float4*>(xrow + 4);
        XDUP(0, 0, a.x); XDUP(0, 1, a.y); XDUP(0, 2, a.z); XDUP(0, 3, a.w);
        XDUP(0, 4, b.x); XDUP(0, 5, b.y); XDUP(0, 6, b.z); XDUP(0, 7, b.w);
    }
    __syncthreads();

    // ---------------- main loop: one barrier per step ----------------
    for (int step = 0; step < NSTEPS; ++step) {
        const int buf = step % 3;
        const int nb  = (step + 1) % 3;
        const bool more = (step + 1 < NSTEPS);

        float4 a, b;
        if (more) {
            const float* xp = xrow + (step + 1) * BK;
            a = *reinterpret_cast<const float4*>(xp + 0);
            b = *reinterpret_cast<const float4*>(xp + 4);
        }

        const float* wsk = ws + (ull)(step * BK) * BN;

        // ---------- compute (register-pipelined LDS) ----------
        ull xv[2][8], wv[2][4];
#define LDK(kk, ph) do {                                                          \
        ulonglong2 xa = *reinterpret_cast<const ulonglong2*>(&XS(buf, kk, rg * 16));      \
        ulonglong2 xb = *reinterpret_cast<const ulonglong2*>(&XS(buf, kk, rg * 16 + 4));  \
        ulonglong2 xc = *reinterpret_cast<const ulonglong2*>(&XS(buf, kk, rg * 16 + 8));  \
        ulonglong2 xd = *reinterpret_cast<const ulonglong2*>(&XS(buf, kk, rg * 16 + 12)); \
        ulonglong2 wa = *reinterpret_cast<const ulonglong2*>(&wsk[(kk) * BN + cg * 4]);   \
        ulonglong2 wb = *reinterpret_cast<const ulonglong2*>(&wsk[(kk) * BN + 64 + cg * 4]); \
        xv[ph][0] = xa.x; xv[ph][1] = xa.y; xv[ph][2] = xb.x; xv[ph][3] = xb.y;   \
        xv[ph][4] = xc.x; xv[ph][5] = xc.y; xv[ph][6] = xd.x; xv[ph][7] = xd.y;   \
        wv[ph][0] = wa.x; wv[ph][1] = wa.y; wv[ph][2] = wb.x; wv[ph][3] = wb.y;   \
    } while (0)

        LDK(0, 0);
#pragma unroll
        for (int k = 0; k < BK; ++k) {
            const int ph  = k & 1;
            const int nph = ph ^ 1;
            if (k + 1 < BK) LDK(k + 1, nph);   // prefetch next k's operands
#pragma unroll
            for (int i = 0; i < 8; ++i) {
#pragma unroll
                for (int j = 0; j < 4; ++j) {
                    ull pr = fmul2(wv[ph][j], xv[ph][i]);          // (-w)*t
                    acc[i][j] = ffma2(acc[i][j], pr, acc[i][j]);   // acc*(1-w*t)
                }
            }
        }
#undef LDK

        if (more) {
            XDUP(nb, 0, a.x); XDUP(nb, 1, a.y); XDUP(nb, 2, a.z); XDUP(nb, 3, a.w);
            XDUP(nb, 4, b.x); XDUP(nb, 5, b.y); XDUP(nb, 6, b.z); XDUP(nb, 7, b.w);
        }
        __syncthreads();
    }

    // ---------------- epilogue: write partial products ----------------
    float* prow = g_part[kz] + (ull)(bm0 + rg * 8) * NUM_OUT + bn * BN + cg * 8;
#pragma unroll
    for (int i = 0; i < 8; ++i) {
        float4 v0, v1;
        v0.x = __uint_as_float((unsigned)(acc[i][0]));
        v0.y = __uint_as_float((unsigned)(acc[i][0] >> 32));
        v0.z = __uint_as_float((unsigned)(acc[i][1]));
        v0.w = __uint_as_float((unsigned)(acc[i][1] >> 32));
        v1.x = __uint_as_float((unsigned)(acc[i][2]));
        v1.y = __uint_as_float((unsigned)(acc[i][2] >> 32));
        v1.z = __uint_as_float((unsigned)(acc[i][3]));
        v1.w = __uint_as_float((unsigned)(acc[i][3] >> 32));
        *reinterpret_cast<float4*>(prow + (ull)i * NUM_OUT)     = v0;
        *reinterpret_cast<float4*>(prow + (ull)i * NUM_OUT + 4) = v1;
    }
#undef XDUP
#undef XS
}

// out = p0 * p1 * p2 * p3 elementwise (float4-vectorized)
__global__ void combine_kernel(float* __restrict__ out) {
    int i = blockIdx.x * blockDim.x + threadIdx.x;
    if (i < (BATCH * NUM_OUT) / 4) {
        float4 a = reinterpret_cast<const float4*>(g_part[0])[i];
        float4 b = reinterpret_cast<const float4*>(g_part[1])[i];
        float4 c = reinterpret_cast<const float4*>(g_part[2])[i];
        float4 d = reinterpret_cast<const float4*>(g_part[3])[i];
        float4 v;
        v.x = (a.x * b.x) * (c.x * d.x);
        v.y = (a.y * b.y) * (c.y * d.y);
        v.z = (a.z * b.z) * (c.z * d.z);
        v.w = (a.w * b.w) * (c.w * d.w);
        reinterpret_cast<float4*>(out)[i] = v;
    }
}

extern "C" void kernel_launch(void* const* d_in, const int* in_sizes, int n_in,
                              void* d_out, int out_size) {
    const float* x    = (const float*)d_in[0];   // [2048, 512]
    const float* Wraw = (const float*)d_in[1];   // [256, 512]
    float* out        = (float*)d_out;           // [2048, 256]

    // idempotent; not a stream op, safe under graph capture
    cudaFuncSetAttribute(logic_kernel,
                         cudaFuncAttributeMaxDynamicSharedMemorySize, SMEM_BYTES);

    dim3 grid(BATCH / BM, NUM_OUT / BN, KSPLIT); // 32 x 2 x 4 = 256 CTAs
    logic_kernel<<<grid, NTHREADS, SMEM_BYTES>>>(x, Wraw);

    combine_kernel<<<(BATCH * NUM_OUT / 4 + 255) / 256, 256>>>(out);
}

// round 17
// speedup vs baseline: 1.0273x; 1.0273x over previous
#include <cuda_runtime.h>
#include <cstdint>
#include <math.h>

#define BATCH   2048
#define IN_DIM  512
#define NUM_OUT 256

#define BM 64
#define BN 128
#define BK 16
#define NTHREADS 128
#define KSPLIT 4
#define KCHUNK (IN_DIM / KSPLIT)    // 128
#define NSTEPS (KCHUNK / BK)        // 8

// dynamic smem: ws[128][128] floats (64KB) + xs[3][BK][132]
#define WS_FLOATS (KCHUNK * BN)               // 16384
#define XS_STRIDE (2 * BM + 4)                // 132
#define XS_FLOATS (3 * BK * XS_STRIDE)        // 6336
#define SMEM_BYTES ((WS_FLOATS + XS_FLOATS) * 4)

typedef unsigned long long ull;

// Partial products per K-chunk: 8 MB
__device__ float g_part[KSPLIT][BATCH * NUM_OUT];

__device__ __forceinline__ ull ffma2(ull a, ull b, ull c) {
    ull d;
    asm("fma.rn.f32x2 %0, %1, %2, %3;" : "=l"(d) : "l"(a), "l"(b), "l"(c));
    return d;
}
__device__ __forceinline__ ull fmul2(ull a, ull b) {
    ull d;
    asm("mul.rn.f32x2 %0, %1, %2;" : "=l"(d) : "l"(a), "l"(b));
    return d;
}

// 64(M) x 128(N) tile per CTA over one 128-K chunk. Thread tile 8x8.
// Sigmoid fused: each CTA builds its own -sigmoid(5W) tile in smem once
// (no precompute kernel, no per-step w traffic). ws row layout is
// piece-permuted: 16B piece p -> phys chunk (p even ? p/2 : 16+p/2), so the
// compute's two w LDS.128 per thread hit contiguous 256B halves.
// xs triple-buffered -> one barrier per step.
__global__ void __launch_bounds__(NTHREADS, 2)
logic_kernel(const float* __restrict__ x, const float* __restrict__ Wraw) {
    extern __shared__ __align__(16) float smem[];
    float* ws  = smem;                // [KCHUNK][BN] piece-permuted per row
    float* xsb = smem + WS_FLOATS;    // [3][BK][XS_STRIDE]
#define XS(b, k, i) xsb[((b) * BK + (k)) * XS_STRIDE + (i)]

    const int tid = threadIdx.x;
    const int bm0 = blockIdx.x * BM;
    const int bn  = blockIdx.y;          // 0..1
    const int kz  = blockIdx.z;          // K-chunk
    const int kbase = kz * KCHUNK;

    const int cg = tid & 15;   // col-group: 8 cols each
    const int rg = tid >> 4;   // row-group: 8 rows each

    // x staging: row xm (0..63), k-half xq (8 k's each)
    const int xm = tid & 63;
    const int xq = tid >> 6;   // 0 or 1
    const int kb = xq * 8;

    const ull ONE2 = 0x3F8000003F800000ULL;
    ull acc[8][4];
#pragma unroll
    for (int i = 0; i < 8; ++i)
#pragma unroll
        for (int j = 0; j < 4; ++j) acc[i][j] = ONE2;

    const float* xrow = x + (ull)(bm0 + xm) * IN_DIM + kbase + xq * 8;

#define XDUP(b, slot, val) do {                                            \
    float2 _p; _p.x = 1.0f - (val); _p.y = _p.x;                           \
    *reinterpret_cast<float2*>(&XS(b, kb + (slot), 2 * xm)) = _p;          \
} while (0)

    // ---------------- prologue ----------------
    {
        // w tile: thread handles logical column f = tid of this CTA's 128-o
        // slice; phys column from inverse piece permutation.
        const float* wrow = Wraw + (ull)(bn * BN + tid) * IN_DIM + kbase;
        const int p = tid >> 2, r = tid & 3;
        const int wcol = (((p & 1) ? 16 + (p >> 1) : (p >> 1)) << 2) + r;
#pragma unroll
        for (int c = 0; c < KCHUNK / 4; ++c) {
            float4 v = *reinterpret_cast<const float4*>(wrow + c * 4);
            ws[(c * 4 + 0) * BN + wcol] = -1.0f / (1.0f + __expf(-5.0f * v.x));
            ws[(c * 4 + 1) * BN + wcol] = -1.0f / (1.0f + __expf(-5.0f * v.y));
            ws[(c * 4 + 2) * BN + wcol] = -1.0f / (1.0f + __expf(-5.0f * v.z));
            ws[(c * 4 + 3) * BN + wcol] = -1.0f / (1.0f + __expf(-5.0f * v.w));
        }
        // x buffer 0
        float4 a = *reinterpret_cast<const float4*>(xrow + 0);
        float4 b = *reinterpret_cast<const float4*>(xrow + 4);
        XDUP(0, 0, a.x); XDUP(0, 1, a.y); XDUP(0, 2, a.z); XDUP(0, 3, a.w);
        XDUP(0, 4, b.x); XDUP(0, 5, b.y); XDUP(0, 6, b.z); XDUP(0, 7, b.w);
    }
    __syncthreads();

    // ---------------- main loop: one barrier per step ----------------
    for (int step = 0; step < NSTEPS; ++step) {
        const int buf = step % 3;
        const int nb  = (step + 1) % 3;
        const bool more = (step + 1 < NSTEPS);

        float4 a, b;
        if (more) {
            const float* xp = xrow + (step + 1) * BK;
            a = *reinterpret_cast<const float4*>(xp + 0);
            b = *reinterpret_cast<const float4*>(xp + 4);
        }

        const float* wsk = ws + (ull)(step * BK) * BN;

        // ---------- compute (register-pipelined LDS) ----------
        ull xv[2][8], wv[2][4];
#define LDK(kk, ph) do {                                                          \
        ulonglong2 xa = *reinterpret_cast<const ulonglong2*>(&XS(buf, kk, rg * 16));      \
        ulonglong2 xb = *reinterpret_cast<const ulonglong2*>(&XS(buf, kk, rg * 16 + 4));  \
        ulonglong2 xc = *reinterpret_cast<const ulonglong2*>(&XS(buf, kk, rg * 16 + 8));  \
        ulonglong2 xd = *reinterpret_cast<const ulonglong2*>(&XS(buf, kk, rg * 16 + 12)); \
        ulonglong2 wa = *reinterpret_cast<const ulonglong2*>(&wsk[(kk) * BN + cg * 4]);   \
        ulonglong2 wb = *reinterpret_cast<const ulonglong2*>(&wsk[(kk) * BN + 64 + cg * 4]); \
        xv[ph][0] = xa.x; xv[ph][1] = xa.y; xv[ph][2] = xb.x; xv[ph][3] = xb.y;   \
        xv[ph][4] = xc.x; xv[ph][5] = xc.y; xv[ph][6] = xd.x; xv[ph][7] = xd.y;   \
        wv[ph][0] = wa.x; wv[ph][1] = wa.y; wv[ph][2] = wb.x; wv[ph][3] = wb.y;   \
    } while (0)

        LDK(0, 0);
#pragma unroll
        for (int k = 0; k < BK; ++k) {
            const int ph  = k & 1;
            const int nph = ph ^ 1;
            if (k + 1 < BK) LDK(k + 1, nph);   // prefetch next k's operands
#pragma unroll
            for (int i = 0; i < 8; ++i) {
#pragma unroll
                for (int j = 0; j < 4; ++j) {
                    ull pr = fmul2(wv[ph][j], xv[ph][i]);          // (-w)*t
                    acc[i][j] = ffma2(acc[i][j], pr, acc[i][j]);   // acc*(1-w*t)
                }
            }
        }
#undef LDK

        if (more) {
            XDUP(nb, 0, a.x); XDUP(nb, 1, a.y); XDUP(nb, 2, a.z); XDUP(nb, 3, a.w);
            XDUP(nb, 4, b.x); XDUP(nb, 5, b.y); XDUP(nb, 6, b.z); XDUP(nb, 7, b.w);
        }
        __syncthreads();
    }

    // ---------------- epilogue: write partial products ----------------
    float* prow = g_part[kz] + (ull)(bm0 + rg * 8) * NUM_OUT + bn * BN + cg * 8;
#pragma unroll
    for (int i = 0; i < 8; ++i) {
        float4 v0, v1;
        v0.x = __uint_as_float((unsigned)(acc[i][0]));
        v0.y = __uint_as_float((unsigned)(acc[i][0] >> 32));
        v0.z = __uint_as_float((unsigned)(acc[i][1]));
        v0.w = __uint_as_float((unsigned)(acc[i][1] >> 32));
        v1.x = __uint_as_float((unsigned)(acc[i][2]));
        v1.y = __uint_as_float((unsigned)(acc[i][2] >> 32));
        v1.z = __uint_as_float((unsigned)(acc[i][3]));
        v1.w = __uint_as_float((unsigned)(acc[i][3] >> 32));
        *reinterpret_cast<float4*>(prow + (ull)i * NUM_OUT)     = v0;
        *reinterpret_cast<float4*>(prow + (ull)i * NUM_OUT + 4) = v1;
    }
#undef XDUP
#undef XS
}

// out = p0 * p1 * p2 * p3 elementwise (float4-vectorized)
__global__ void combine_kernel(float* __restrict__ out) {
    int i = blockIdx.x * blockDim.x + threadIdx.x;
    if (i < (BATCH * NUM_OUT) / 4) {
        float4 a = reinterpret_cast<const float4*>(g_part[0])[i];
        float4 b = reinterpret_cast<const float4*>(g_part[1])[i];
        float4 c = reinterpret_cast<const float4*>(g_part[2])[i];
        float4 d = reinterpret_cast<const float4*>(g_part[3])[i];
        float4 v;
        v.x = (a.x * b.x) * (c.x * d.x);
        v.y = (a.y * b.y) * (c.y * d.y);
        v.z = (a.z * b.z) * (c.z * d.z);
        v.w = (a.w * b.w) * (c.w * d.w);
        reinterpret_cast<float4*>(out)[i] = v;
    }
}

extern "C" void kernel_launch(void* const* d_in, const int* in_sizes, int n_in,
                              void* d_out, int out_size) {
    const float* x    = (const float*)d_in[0];   // [2048, 512]
    const float* Wraw = (const float*)d_in[1];   // [256, 512]
    float* out        = (float*)d_out;           // [2048, 256]

    // idempotent; not a stream op, safe under graph capture
    cudaFuncSetAttribute(logic_kernel,
                         cudaFuncAttributeMaxDynamicSharedMemorySize, SMEM_BYTES);

    dim3 grid(BATCH / BM, NUM_OUT / BN, KSPLIT); // 32 x 2 x 4 = 256 CTAs
    logic_kernel<<<grid, NTHREADS, SMEM_BYTES>>>(x, Wraw);

    combine_kernel<<<(BATCH * NUM_OUT / 4 + 255) / 256, 256>>>(out);
}